// round 3
// baseline (speedup 1.0000x reference)
#include <cuda_runtime.h>
#include <cuda_fp16.h>
#include <cstdint>

#define NF    10240
#define CDIM  64      // B*DOUT = 4*16 packed batch-output columns
#define KSPLIT 8
#define KPER  (NF / KSPLIT)   // 1280
#define MTILE 128
#define GS_PITCH 36   // words per row of G smem tile (conflict-free: 4n+c' distinct)

// -------- device scratch (allocation-free rule: static __device__ arrays) ----
__device__ float  g_H0T[CDIM * NF];          // H0 transposed: [c][i]  (2.6 MB)
__device__ float  g_degPart[128 * NF];       // column-sum partials    (5.2 MB)
__device__ float  g_dinv[NF];
__device__ float  g_diagfix[NF];             // 1.0 if supports[j,j]==0 else 0
__device__ __half g_GT[CDIM * NF];           // G transposed fp16: [c][i] (1.3 MB)
__device__ float  g_Ppart[KSPLIT * NF * CDIM]; // split-K partials     (21 MB)

// ---------------------------------------------------------------- K0: H0^T --
// H0[i,c] = sum_d x[b,i,d] * W_gcn[d,o],  c = b*16+o.  Stored transposed [c][i].
__global__ void k0_h0t(const float* __restrict__ x, const float* __restrict__ Wg) {
    __shared__ float W[256];
    if (threadIdx.x < 256) W[threadIdx.x] = Wg[threadIdx.x];
    __syncthreads();
    int i = blockIdx.x * 256 + threadIdx.x;
    #pragma unroll
    for (int b = 0; b < 4; ++b) {
        float xv[16];
        const float4* px = reinterpret_cast<const float4*>(x + ((size_t)b * NF + i) * 16);
        #pragma unroll
        for (int q = 0; q < 4; ++q) {
            float4 v = px[q];
            xv[q*4+0] = v.x; xv[q*4+1] = v.y; xv[q*4+2] = v.z; xv[q*4+3] = v.w;
        }
        #pragma unroll
        for (int o = 0; o < 16; ++o) {
            float s = 0.f;
            #pragma unroll
            for (int d = 0; d < 16; ++d) s += xv[d] * W[d * 16 + o];
            g_H0T[(b * 16 + o) * NF + i] = s;
        }
    }
}

// --------------------------------------------------- K1: deg column partials --
// grid (10, 128): block sums 80 rows for 1024 columns (float4 per thread).
__global__ void k1_degpart(const float* __restrict__ S) {
    int j4 = blockIdx.x * 1024 + threadIdx.x * 4;
    int r  = blockIdx.y;
    const float* p = S + (size_t)r * 80 * NF + j4;
    float4 acc = make_float4(0.f, 0.f, 0.f, 0.f);
    #pragma unroll 8
    for (int it = 0; it < 80; ++it) {
        float4 v = *reinterpret_cast<const float4*>(p);
        acc.x += v.x; acc.y += v.y; acc.z += v.z; acc.w += v.w;
        p += NF;
    }
    *reinterpret_cast<float4*>(&g_degPart[r * NF + j4]) = acc;
}

// ------------------------------------------------------- K2a: dinv + diagfix --
__global__ void k2a_dinv(const float* __restrict__ S) {
    int j = blockIdx.x * 256 + threadIdx.x;
    float s = 0.f;
    #pragma unroll 8
    for (int r = 0; r < 128; ++r) s += g_degPart[r * NF + j];
    float dv  = S[(size_t)j * NF + j];
    float fix = (dv == 0.0f) ? 1.0f : 0.0f;   // add_remaining_self_loops
    s += fix;
    g_diagfix[j] = fix;
    g_dinv[j] = (s > 0.f) ? rsqrtf(s) : 0.f;
}

// ----------------------------------------------------------- K2b: G^T (fp16) --
__global__ void k2b_gt(int dummy) {
    int i = blockIdx.x * 256 + threadIdx.x;
    int c = blockIdx.y;
    g_GT[c * NF + i] = __float2half_rn(g_dinv[i] * g_H0T[c * NF + i]);
}

// --------------------------------------------------------------- K3: GEMM ----
// P[j,c] = sum_i A[i,j] * G[i,c];  M=10240(j), N=64(c), K=10240(i), split-K=8.
// A fragments loaded directly from gmem (fp32 -> fp16 pack). G tile in SMEM.
__device__ __forceinline__ uint32_t pack_f16x2(float lo, float hi) {
    __half2 h = __floats2half2_rn(lo, hi);
    return *reinterpret_cast<uint32_t*>(&h);
}

__global__ __launch_bounds__(256, 3) void k3_gemm(const float* __restrict__ A) {
    __shared__ uint32_t Gs[CDIM * GS_PITCH];   // 9216 B

    const int tid  = threadIdx.x;
    const int warp = tid >> 5;
    const int lane = tid & 31;
    const int g    = lane >> 2;   // groupID (row within m16 / n within n8)
    const int t4   = lane & 3;    // threadID_in_group

    const int j0     = blockIdx.x * MTILE;
    const int kb     = blockIdx.y;
    const int kbase0 = kb * KPER;
    const int jr     = j0 + warp * 16 + g;

    float acc[8][4];
    #pragma unroll
    for (int nb = 0; nb < 8; ++nb)
        #pragma unroll
        for (int q = 0; q < 4; ++q) acc[nb][q] = 0.f;

    const float* Aj = A + jr;

    for (int st = 0; st < KPER / 64; ++st) {   // 20 stages of K=64
        const int kst = kbase0 + st * 64;
        __syncthreads();
        {   // stage G^T tile: 64 rows (c) x 64 halves (k), conflict-free pitch
            int row = tid >> 2;
            int m   = tid & 3;
            const uint4* src = reinterpret_cast<const uint4*>(g_GT + (size_t)row * NF + kst) + m * 2;
            uint4 v0 = src[0];
            uint4 v1 = src[1];
            uint32_t* dst = Gs + row * GS_PITCH + m * 8;
            *reinterpret_cast<uint4*>(dst)     = v0;
            *reinterpret_cast<uint4*>(dst + 4) = v1;
        }
        __syncthreads();

        #pragma unroll
        for (int s = 0; s < 4; ++s) {          // 4 x k16 steps
            const int kc = kst + s * 16 + 2 * t4;
            const float* pa = Aj + kc * NF;
            const float* pb = pa + 8 * NF;
            // A fragment: rows {g, g+8}(j), cols {2t,2t+1,2t+8,2t+9}(k)
            float a00 = pa[0],      a01 = pa[NF];
            float a80 = pa[8],      a81 = pa[NF + 8];
            float b00 = pb[0],      b01 = pb[NF];
            float b80 = pb[8],      b81 = pb[NF + 8];
            uint32_t af0 = pack_f16x2(a00, a01);   // (g,   k),(g,   k+1)
            uint32_t af1 = pack_f16x2(a80, a81);   // (g+8, k),(g+8, k+1)
            uint32_t af2 = pack_f16x2(b00, b01);   // (g,   k+8),(g, k+9)
            uint32_t af3 = pack_f16x2(b80, b81);   // (g+8, k+8),...

            const int bw = s * 8 + t4;
            #pragma unroll
            for (int nb = 0; nb < 8; ++nb) {
                const int nrow = nb * 8 + g;
                uint32_t bf0 = Gs[nrow * GS_PITCH + bw];        // B[2t..2t+1][n]
                uint32_t bf1 = Gs[nrow * GS_PITCH + bw + 4];    // B[2t+8..2t+9][n]
                asm volatile(
                    "mma.sync.aligned.m16n8k16.row.col.f32.f16.f16.f32 "
                    "{%0,%1,%2,%3}, {%4,%5,%6,%7}, {%8,%9}, {%0,%1,%2,%3};\n"
                    : "+f"(acc[nb][0]), "+f"(acc[nb][1]),
                      "+f"(acc[nb][2]), "+f"(acc[nb][3])
                    : "r"(af0), "r"(af1), "r"(af2), "r"(af3),
                      "r"(bf0), "r"(bf1));
            }
        }
    }

    float* P = g_Ppart + (size_t)kb * NF * CDIM;
    #pragma unroll
    for (int nb = 0; nb < 8; ++nb) {
        int cc = nb * 8 + 2 * t4;
        *reinterpret_cast<float2*>(&P[(size_t)jr * CDIM + cc]) =
            make_float2(acc[nb][0], acc[nb][1]);
        *reinterpret_cast<float2*>(&P[(size_t)(jr + 8) * CDIM + cc]) =
            make_float2(acc[nb][2], acc[nb][3]);
    }
}

// ------------------------------------------------------------- K4: epilogue --
// reduce split-K, diag fixup, h = relu(dinv[j]*P + b_gcn), out = h @ W_out + b_out
__global__ void k4_epilogue(const float* __restrict__ b_gcn,
                            const float* __restrict__ Wout,
                            const float* __restrict__ bout,
                            float* __restrict__ out) {
    __shared__ float hs[160];
    __shared__ float Ws[2560];
    const int n = blockIdx.x;
    const int b = blockIdx.y;
    const int t = threadIdx.x;

    for (int q = t; q < 2560; q += 160) Ws[q] = Wout[q];

    const int f  = t / 16;
    const int o1 = t % 16;
    const int j  = n * 10 + f;
    const int c  = b * 16 + o1;

    float p = 0.f;
    #pragma unroll
    for (int s = 0; s < KSPLIT; ++s)
        p += g_Ppart[((size_t)s * NF + j) * CDIM + c];
    if (g_diagfix[j] != 0.f)                      // self-loop weight 1 on zero diag
        p += g_dinv[j] * g_H0T[c * NF + j];
    float h = g_dinv[j] * p + b_gcn[o1];
    hs[t] = fmaxf(h, 0.f);
    __syncthreads();

    if (t < 16) {
        float acc = bout[t];
        #pragma unroll 8
        for (int q = 0; q < 160; ++q) acc += hs[q] * Ws[q * 16 + t];
        out[((size_t)b * 1024 + n) * 16 + t] = acc;
    }
}

// ------------------------------------------------------------------ launch ---
extern "C" void kernel_launch(void* const* d_in, const int* in_sizes, int n_in,
                              void* d_out, int out_size) {
    const float* x        = (const float*)d_in[0];  // (4,1024,10,16)
    const float* supports = (const float*)d_in[3];  // (10240,10240)
    const float* W_gcn    = (const float*)d_in[6];  // (16,16)
    const float* b_gcn    = (const float*)d_in[7];  // (16,)
    const float* W_out    = (const float*)d_in[8];  // (160,16)
    const float* b_out    = (const float*)d_in[9];  // (16,)
    float* out = (float*)d_out;

    k0_h0t<<<NF / 256, 256>>>(x, W_gcn);
    k1_degpart<<<dim3(NF / 1024, 128), 256>>>(supports);
    k2a_dinv<<<NF / 256, 256>>>(supports);
    k2b_gt<<<dim3(NF / 256, CDIM), 256>>>(0);
    k3_gemm<<<dim3(NF / MTILE, KSPLIT), 256>>>(supports);
    k4_epilogue<<<dim3(1024, 4), 160>>>(b_gcn, W_out, b_out, out);
}

// round 4
// speedup vs baseline: 1.1014x; 1.1014x over previous
#include <cuda_runtime.h>
#include <cuda_fp16.h>
#include <cstdint>

#define NF    10240
#define CDIM  64      // B*DOUT = 4*16 packed batch-output columns
#define KSPLIT 8
#define KPER  (NF / KSPLIT)   // 1280
#define MTILE 128
#define KTILE 32
#define NSTAGES (KPER / KTILE)   // 40
#define AS_PITCH 132  // fp32 words per A smem row (conflict-free: (8*t4+g) distinct)
#define GS_PITCH 20   // uint32 words per G smem row (conflict-free: (20g+t4)%32 distinct)

// -------- device scratch (allocation-free rule: static __device__ arrays) ----
__device__ float  g_H0T[CDIM * NF];          // H0 transposed: [c][i]  (2.6 MB)
__device__ float  g_degPart[128 * NF];       // column-sum partials    (5.2 MB)
__device__ float  g_dinv[NF];
__device__ float  g_diagfix[NF];             // 1.0 if supports[j,j]==0 else 0
__device__ __half g_GT[CDIM * NF];           // G transposed fp16: [c][i] (1.3 MB)
__device__ float  g_Ppart[KSPLIT * NF * CDIM]; // split-K partials     (21 MB)

// ---------------------------------------------------------------- K0: H0^T --
__global__ void k0_h0t(const float* __restrict__ x, const float* __restrict__ Wg) {
    __shared__ float W[256];
    if (threadIdx.x < 256) W[threadIdx.x] = Wg[threadIdx.x];
    __syncthreads();
    int i = blockIdx.x * 256 + threadIdx.x;
    #pragma unroll
    for (int b = 0; b < 4; ++b) {
        float xv[16];
        const float4* px = reinterpret_cast<const float4*>(x + ((size_t)b * NF + i) * 16);
        #pragma unroll
        for (int q = 0; q < 4; ++q) {
            float4 v = px[q];
            xv[q*4+0] = v.x; xv[q*4+1] = v.y; xv[q*4+2] = v.z; xv[q*4+3] = v.w;
        }
        #pragma unroll
        for (int o = 0; o < 16; ++o) {
            float s = 0.f;
            #pragma unroll
            for (int d = 0; d < 16; ++d) s += xv[d] * W[d * 16 + o];
            g_H0T[(b * 16 + o) * NF + i] = s;
        }
    }
}

// --------------------------------------------------- K1: deg column partials --
__global__ void k1_degpart(const float* __restrict__ S) {
    int j4 = blockIdx.x * 1024 + threadIdx.x * 4;
    int r  = blockIdx.y;
    const float* p = S + (size_t)r * 80 * NF + j4;
    float4 acc = make_float4(0.f, 0.f, 0.f, 0.f);
    #pragma unroll 8
    for (int it = 0; it < 80; ++it) {
        float4 v = *reinterpret_cast<const float4*>(p);
        acc.x += v.x; acc.y += v.y; acc.z += v.z; acc.w += v.w;
        p += NF;
    }
    *reinterpret_cast<float4*>(&g_degPart[r * NF + j4]) = acc;
}

// ------------------------------------------------------- K2a: dinv + diagfix --
__global__ void k2a_dinv(const float* __restrict__ S) {
    int j = blockIdx.x * 256 + threadIdx.x;
    float s = 0.f;
    #pragma unroll 8
    for (int r = 0; r < 128; ++r) s += g_degPart[r * NF + j];
    float dv  = S[(size_t)j * NF + j];
    float fix = (dv == 0.0f) ? 1.0f : 0.0f;   // add_remaining_self_loops
    s += fix;
    g_diagfix[j] = fix;
    g_dinv[j] = (s > 0.f) ? rsqrtf(s) : 0.f;
}

// ----------------------------------------------------------- K2b: G^T (fp16) --
__global__ void k2b_gt(int dummy) {
    int i = (blockIdx.x * 256 + threadIdx.x) * 4;
    int c = blockIdx.y;
    float4 h = *reinterpret_cast<const float4*>(&g_H0T[(size_t)c * NF + i]);
    float4 dv = *reinterpret_cast<const float4*>(&g_dinv[i]);
    __half2 lo = __floats2half2_rn(h.x * dv.x, h.y * dv.y);
    __half2 hi = __floats2half2_rn(h.z * dv.z, h.w * dv.w);
    uint2 out;
    out.x = *reinterpret_cast<uint32_t*>(&lo);
    out.y = *reinterpret_cast<uint32_t*>(&hi);
    *reinterpret_cast<uint2*>(&g_GT[(size_t)c * NF + i]) = out;
}

// --------------------------------------------------------------- K3: GEMM ----
// P[j,c] = sum_i A[i,j] * G[i,c];  M=10240(j), N=64(c), K=10240(i), split-K=8.
// cp.async double-buffered: A tile (fp32, 32k x 128j) + G tile (fp16) in SMEM.
__device__ __forceinline__ uint32_t pack_f16x2(float lo, float hi) {
    __half2 h = __floats2half2_rn(lo, hi);
    return *reinterpret_cast<uint32_t*>(&h);
}
__device__ __forceinline__ void cp_async16(uint32_t dst, const void* src) {
    asm volatile("cp.async.cg.shared.global [%0], [%1], 16;\n" :: "r"(dst), "l"(src));
}
#define CP_COMMIT() asm volatile("cp.async.commit_group;\n" ::: "memory")
#define CP_WAIT(n)  asm volatile("cp.async.wait_group %0;\n" :: "n"(n) : "memory")

__global__ __launch_bounds__(256) void k3_gemm(const float* __restrict__ A) {
    __shared__ float    As[2][KTILE * AS_PITCH];   // 33.8 KB
    __shared__ uint32_t Gs[2][CDIM * GS_PITCH];    // 10.2 KB

    const int tid  = threadIdx.x;
    const int warp = tid >> 5;
    const int lane = tid & 31;
    const int g    = lane >> 2;   // groupID
    const int t4   = lane & 3;    // threadID_in_group

    const int j0     = blockIdx.x * MTILE;
    const int kb     = blockIdx.y;
    const int kbase0 = kb * KPER;
    const int jr     = j0 + warp * 16 + g;

    const uint32_t asA0 = (uint32_t)__cvta_generic_to_shared(&As[0][0]);
    const uint32_t asA1 = (uint32_t)__cvta_generic_to_shared(&As[1][0]);
    const uint32_t asG0 = (uint32_t)__cvta_generic_to_shared(&Gs[0][0]);
    const uint32_t asG1 = (uint32_t)__cvta_generic_to_shared(&Gs[1][0]);

    // per-thread copy coordinates
    const int rowA = tid >> 5;          // 0..7   (A: 32 threads per 512B row)
    const int offA = (tid & 31) * 4;    // float offset within row
    const int rowG = tid >> 2;          // 0..63  (G: 4 threads per 64B row)
    const int offG = (tid & 3) * 8;     // half offset within row

    float acc[8][4];
    #pragma unroll
    for (int nb = 0; nb < 8; ++nb)
        #pragma unroll
        for (int q = 0; q < 4; ++q) acc[nb][q] = 0.f;

    auto load_stage = [&](int st, int buf) {
        const int kst = kbase0 + st * KTILE;
        const uint32_t dA = buf ? asA1 : asA0;
        const uint32_t dG = buf ? asG1 : asG0;
        #pragma unroll
        for (int p = 0; p < 4; ++p) {
            int r = rowA + p * 8;
            cp_async16(dA + (uint32_t)(r * AS_PITCH + offA) * 4,
                       A + (size_t)(kst + r) * NF + j0 + offA);
        }
        cp_async16(dG + (uint32_t)rowG * (GS_PITCH * 4) + (tid & 3) * 16,
                   g_GT + (size_t)rowG * NF + kst + offG);
        CP_COMMIT();
    };

    load_stage(0, 0);

    for (int st = 0; st < NSTAGES; ++st) {
        const int buf = st & 1;
        if (st + 1 < NSTAGES) {
            load_stage(st + 1, buf ^ 1);
            CP_WAIT(1);
        } else {
            CP_WAIT(0);
        }
        __syncthreads();

        const float*    as = As[buf];
        const uint32_t* gs = Gs[buf];
        const int col = warp * 16 + g;

        #pragma unroll
        for (int s = 0; s < 2; ++s) {          // 2 x k16 steps
            const int kr = s * 16 + 2 * t4;
            float x0 = as[kr * AS_PITCH + col];
            float x1 = as[(kr + 1) * AS_PITCH + col];
            float x2 = as[kr * AS_PITCH + col + 8];
            float x3 = as[(kr + 1) * AS_PITCH + col + 8];
            float y0 = as[(kr + 8) * AS_PITCH + col];
            float y1 = as[(kr + 9) * AS_PITCH + col];
            float y2 = as[(kr + 8) * AS_PITCH + col + 8];
            float y3 = as[(kr + 9) * AS_PITCH + col + 8];
            uint32_t af0 = pack_f16x2(x0, x1);   // (j=g,   k, k+1)
            uint32_t af1 = pack_f16x2(x2, x3);   // (j=g+8, k, k+1)
            uint32_t af2 = pack_f16x2(y0, y1);   // (j=g,   k+8, k+9)
            uint32_t af3 = pack_f16x2(y2, y3);   // (j=g+8, k+8, k+9)

            const int bw = s * 8 + t4;
            #pragma unroll
            for (int nb = 0; nb < 8; ++nb) {
                const int nrow = nb * 8 + g;
                uint32_t bf0 = gs[nrow * GS_PITCH + bw];
                uint32_t bf1 = gs[nrow * GS_PITCH + bw + 4];
                asm volatile(
                    "mma.sync.aligned.m16n8k16.row.col.f32.f16.f16.f32 "
                    "{%0,%1,%2,%3}, {%4,%5,%6,%7}, {%8,%9}, {%0,%1,%2,%3};\n"
                    : "+f"(acc[nb][0]), "+f"(acc[nb][1]),
                      "+f"(acc[nb][2]), "+f"(acc[nb][3])
                    : "r"(af0), "r"(af1), "r"(af2), "r"(af3),
                      "r"(bf0), "r"(bf1));
            }
        }
        __syncthreads();
    }

    float* P = g_Ppart + (size_t)kb * NF * CDIM;
    #pragma unroll
    for (int nb = 0; nb < 8; ++nb) {
        int cc = nb * 8 + 2 * t4;
        *reinterpret_cast<float2*>(&P[(size_t)jr * CDIM + cc]) =
            make_float2(acc[nb][0], acc[nb][1]);
        *reinterpret_cast<float2*>(&P[(size_t)(jr + 8) * CDIM + cc]) =
            make_float2(acc[nb][2], acc[nb][3]);
    }
}

// ------------------------------------------------------------- K4: epilogue --
__global__ void k4_epilogue(const float* __restrict__ b_gcn,
                            const float* __restrict__ Wout,
                            const float* __restrict__ bout,
                            float* __restrict__ out) {
    __shared__ float hs[160];
    __shared__ float Ws[2560];
    const int n = blockIdx.x;
    const int b = blockIdx.y;
    const int t = threadIdx.x;

    for (int q = t; q < 2560; q += 160) Ws[q] = Wout[q];

    const int f  = t / 16;
    const int o1 = t % 16;
    const int j  = n * 10 + f;
    const int c  = b * 16 + o1;

    float p = 0.f;
    #pragma unroll
    for (int s = 0; s < KSPLIT; ++s)
        p += g_Ppart[((size_t)s * NF + j) * CDIM + c];
    if (g_diagfix[j] != 0.f)                      // self-loop weight 1 on zero diag
        p += g_dinv[j] * g_H0T[c * NF + j];
    float h = g_dinv[j] * p + b_gcn[o1];
    hs[t] = fmaxf(h, 0.f);
    __syncthreads();

    if (t < 16) {
        float acc = bout[t];
        #pragma unroll 8
        for (int q = 0; q < 160; ++q) acc += hs[q] * Ws[q * 16 + t];
        out[((size_t)b * 1024 + n) * 16 + t] = acc;
    }
}

// ------------------------------------------------------------------ launch ---
extern "C" void kernel_launch(void* const* d_in, const int* in_sizes, int n_in,
                              void* d_out, int out_size) {
    const float* x        = (const float*)d_in[0];  // (4,1024,10,16)
    const float* supports = (const float*)d_in[3];  // (10240,10240)
    const float* W_gcn    = (const float*)d_in[6];  // (16,16)
    const float* b_gcn    = (const float*)d_in[7];  // (16,)
    const float* W_out    = (const float*)d_in[8];  // (160,16)
    const float* b_out    = (const float*)d_in[9];  // (16,)
    float* out = (float*)d_out;

    k0_h0t<<<NF / 256, 256>>>(x, W_gcn);
    k1_degpart<<<dim3(NF / 1024, 128), 256>>>(supports);
    k2a_dinv<<<NF / 256, 256>>>(supports);
    k2b_gt<<<dim3(NF / 1024, CDIM), 256>>>(0);
    k3_gemm<<<dim3(NF / MTILE, KSPLIT), 256>>>(supports);
    k4_epilogue<<<dim3(1024, 4), 160>>>(b_gcn, W_out, b_out, out);
}

// round 5
// speedup vs baseline: 1.1030x; 1.0014x over previous
#include <cuda_runtime.h>
#include <cuda_fp16.h>
#include <cstdint>

#define NF    10240
#define CDIM  64      // B*DOUT = 4*16 packed batch-output columns
#define KSPLIT 8
#define KPER  (NF / KSPLIT)   // 1280
#define MTILE 128
#define KTILE 32
#define NSTAGES (KPER / KTILE)   // 40
#define AS_PITCH 132  // fp32 words per A smem row (conflict-free: (8*t4+g) distinct)
#define GS_PITCH 20   // uint32 words per G smem row (conflict-free: (20g+t4)%32 distinct)

// -------- device scratch (allocation-free rule: static __device__ arrays) ----
__device__ float  g_H0T[CDIM * NF];          // H0 transposed: [c][i]  (2.6 MB)
__device__ float  g_degPart[128 * NF];       // column-sum partials    (5.2 MB)
__device__ float  g_dinv[NF];
__device__ float  g_diagfix[NF];             // 1.0 if supports[j,j]==0 else 0
__device__ __half g_GT[CDIM * NF];           // G transposed fp16: [c][i] (1.3 MB)
__device__ float  g_Ppart[KSPLIT * NF * CDIM]; // split-K partials     (21 MB)

// ---------------------------------------------------------------- K0: H0^T --
__global__ void k0_h0t(const float* __restrict__ x, const float* __restrict__ Wg) {
    __shared__ float W[256];
    if (threadIdx.x < 256) W[threadIdx.x] = Wg[threadIdx.x];
    __syncthreads();
    int i = blockIdx.x * 256 + threadIdx.x;
    #pragma unroll
    for (int b = 0; b < 4; ++b) {
        float xv[16];
        const float4* px = reinterpret_cast<const float4*>(x + ((size_t)b * NF + i) * 16);
        #pragma unroll
        for (int q = 0; q < 4; ++q) {
            float4 v = px[q];
            xv[q*4+0] = v.x; xv[q*4+1] = v.y; xv[q*4+2] = v.z; xv[q*4+3] = v.w;
        }
        #pragma unroll
        for (int o = 0; o < 16; ++o) {
            float s = 0.f;
            #pragma unroll
            for (int d = 0; d < 16; ++d) s += xv[d] * W[d * 16 + o];
            g_H0T[(b * 16 + o) * NF + i] = s;
        }
    }
}

// --------------------------------------------------- K1: deg column partials --
__global__ void k1_degpart(const float* __restrict__ S) {
    int j4 = blockIdx.x * 1024 + threadIdx.x * 4;
    int r  = blockIdx.y;
    const float* p = S + (size_t)r * 80 * NF + j4;
    float4 acc = make_float4(0.f, 0.f, 0.f, 0.f);
    #pragma unroll 8
    for (int it = 0; it < 80; ++it) {
        float4 v = *reinterpret_cast<const float4*>(p);
        acc.x += v.x; acc.y += v.y; acc.z += v.z; acc.w += v.w;
        p += NF;
    }
    *reinterpret_cast<float4*>(&g_degPart[r * NF + j4]) = acc;
}

// ------------------------------------------------------- K2a: dinv + diagfix --
__global__ void k2a_dinv(const float* __restrict__ S) {
    int j = blockIdx.x * 256 + threadIdx.x;
    float s = 0.f;
    #pragma unroll 8
    for (int r = 0; r < 128; ++r) s += g_degPart[r * NF + j];
    float dv  = S[(size_t)j * NF + j];
    float fix = (dv == 0.0f) ? 1.0f : 0.0f;   // add_remaining_self_loops
    s += fix;
    g_diagfix[j] = fix;
    g_dinv[j] = (s > 0.f) ? rsqrtf(s) : 0.f;
}

// ----------------------------------------------------------- K2b: G^T (fp16) --
__global__ void k2b_gt(int dummy) {
    int i = (blockIdx.x * 256 + threadIdx.x) * 4;
    int c = blockIdx.y;
    float4 h = *reinterpret_cast<const float4*>(&g_H0T[(size_t)c * NF + i]);
    float4 dv = *reinterpret_cast<const float4*>(&g_dinv[i]);
    __half2 lo = __floats2half2_rn(h.x * dv.x, h.y * dv.y);
    __half2 hi = __floats2half2_rn(h.z * dv.z, h.w * dv.w);
    uint2 out;
    out.x = *reinterpret_cast<uint32_t*>(&lo);
    out.y = *reinterpret_cast<uint32_t*>(&hi);
    *reinterpret_cast<uint2*>(&g_GT[(size_t)c * NF + i]) = out;
}

// --------------------------------------------------------------- K3: GEMM ----
// P[j,c] = sum_i A[i,j] * G[i,c];  M=10240(j), N=64(c), K=10240(i), split-K=8.
// cp.async double-buffered: A tile (fp32, 32k x 128j) + G tile (fp16) in SMEM.
__device__ __forceinline__ uint32_t pack_f16x2(float lo, float hi) {
    __half2 h = __floats2half2_rn(lo, hi);
    return *reinterpret_cast<uint32_t*>(&h);
}
__device__ __forceinline__ void cp_async16(uint32_t dst, const void* src) {
    asm volatile("cp.async.cg.shared.global [%0], [%1], 16;\n" :: "r"(dst), "l"(src));
}
#define CP_COMMIT() asm volatile("cp.async.commit_group;\n" ::: "memory")
#define CP_WAIT(n)  asm volatile("cp.async.wait_group %0;\n" :: "n"(n) : "memory")

__global__ __launch_bounds__(256) void k3_gemm(const float* __restrict__ A) {
    __shared__ float    As[2][KTILE * AS_PITCH];   // 33.8 KB
    __shared__ uint32_t Gs[2][CDIM * GS_PITCH];    // 10.2 KB

    const int tid  = threadIdx.x;
    const int warp = tid >> 5;
    const int lane = tid & 31;
    const int g    = lane >> 2;   // groupID
    const int t4   = lane & 3;    // threadID_in_group

    const int j0     = blockIdx.x * MTILE;
    const int kb     = blockIdx.y;
    const int kbase0 = kb * KPER;
    const int jr     = j0 + warp * 16 + g;

    const uint32_t asA0 = (uint32_t)__cvta_generic_to_shared(&As[0][0]);
    const uint32_t asA1 = (uint32_t)__cvta_generic_to_shared(&As[1][0]);
    const uint32_t asG0 = (uint32_t)__cvta_generic_to_shared(&Gs[0][0]);
    const uint32_t asG1 = (uint32_t)__cvta_generic_to_shared(&Gs[1][0]);

    // per-thread copy coordinates
    const int rowA = tid >> 5;          // 0..7   (A: 32 threads per 512B row)
    const int offA = (tid & 31) * 4;    // float offset within row
    const int rowG = tid >> 2;          // 0..63  (G: 4 threads per 64B row)
    const int offG = (tid & 3) * 8;     // half offset within row

    float acc[8][4];
    #pragma unroll
    for (int nb = 0; nb < 8; ++nb)
        #pragma unroll
        for (int q = 0; q < 4; ++q) acc[nb][q] = 0.f;

    auto load_stage = [&](int st, int buf) {
        const int kst = kbase0 + st * KTILE;
        const uint32_t dA = buf ? asA1 : asA0;
        const uint32_t dG = buf ? asG1 : asG0;
        #pragma unroll
        for (int p = 0; p < 4; ++p) {
            int r = rowA + p * 8;
            cp_async16(dA + (uint32_t)(r * AS_PITCH + offA) * 4,
                       A + (size_t)(kst + r) * NF + j0 + offA);
        }
        cp_async16(dG + (uint32_t)rowG * (GS_PITCH * 4) + (tid & 3) * 16,
                   g_GT + (size_t)rowG * NF + kst + offG);
        CP_COMMIT();
    };

    load_stage(0, 0);

    for (int st = 0; st < NSTAGES; ++st) {
        const int buf = st & 1;
        if (st + 1 < NSTAGES) {
            load_stage(st + 1, buf ^ 1);
            CP_WAIT(1);
        } else {
            CP_WAIT(0);
        }
        __syncthreads();

        const float*    as = As[buf];
        const uint32_t* gs = Gs[buf];
        const int col = warp * 16 + g;

        #pragma unroll
        for (int s = 0; s < 2; ++s) {          // 2 x k16 steps
            const int kr = s * 16 + 2 * t4;
            float x0 = as[kr * AS_PITCH + col];
            float x1 = as[(kr + 1) * AS_PITCH + col];
            float x2 = as[kr * AS_PITCH + col + 8];
            float x3 = as[(kr + 1) * AS_PITCH + col + 8];
            float y0 = as[(kr + 8) * AS_PITCH + col];
            float y1 = as[(kr + 9) * AS_PITCH + col];
            float y2 = as[(kr + 8) * AS_PITCH + col + 8];
            float y3 = as[(kr + 9) * AS_PITCH + col + 8];
            uint32_t af0 = pack_f16x2(x0, x1);   // (j=g,   k, k+1)
            uint32_t af1 = pack_f16x2(x2, x3);   // (j=g+8, k, k+1)
            uint32_t af2 = pack_f16x2(y0, y1);   // (j=g,   k+8, k+9)
            uint32_t af3 = pack_f16x2(y2, y3);   // (j=g+8, k+8, k+9)

            const int bw = s * 8 + t4;
            #pragma unroll
            for (int nb = 0; nb < 8; ++nb) {
                const int nrow = nb * 8 + g;
                uint32_t bf0 = gs[nrow * GS_PITCH + bw];
                uint32_t bf1 = gs[nrow * GS_PITCH + bw + 4];
                asm volatile(
                    "mma.sync.aligned.m16n8k16.row.col.f32.f16.f16.f32 "
                    "{%0,%1,%2,%3}, {%4,%5,%6,%7}, {%8,%9}, {%0,%1,%2,%3};\n"
                    : "+f"(acc[nb][0]), "+f"(acc[nb][1]),
                      "+f"(acc[nb][2]), "+f"(acc[nb][3])
                    : "r"(af0), "r"(af1), "r"(af2), "r"(af3),
                      "r"(bf0), "r"(bf1));
            }
        }
        __syncthreads();
    }

    float* P = g_Ppart + (size_t)kb * NF * CDIM;
    #pragma unroll
    for (int nb = 0; nb < 8; ++nb) {
        int cc = nb * 8 + 2 * t4;
        *reinterpret_cast<float2*>(&P[(size_t)jr * CDIM + cc]) =
            make_float2(acc[nb][0], acc[nb][1]);
        *reinterpret_cast<float2*>(&P[(size_t)(jr + 8) * CDIM + cc]) =
            make_float2(acc[nb][2], acc[nb][3]);
    }
}

// ------------------------------------------------------------- K4: epilogue --
__global__ void k4_epilogue(const float* __restrict__ b_gcn,
                            const float* __restrict__ Wout,
                            const float* __restrict__ bout,
                            float* __restrict__ out) {
    __shared__ float hs[160];
    __shared__ float Ws[2560];
    const int n = blockIdx.x;
    const int b = blockIdx.y;
    const int t = threadIdx.x;

    for (int q = t; q < 2560; q += 160) Ws[q] = Wout[q];

    const int f  = t / 16;
    const int o1 = t % 16;
    const int j  = n * 10 + f;
    const int c  = b * 16 + o1;

    float p = 0.f;
    #pragma unroll
    for (int s = 0; s < KSPLIT; ++s)
        p += g_Ppart[((size_t)s * NF + j) * CDIM + c];
    if (g_diagfix[j] != 0.f)                      // self-loop weight 1 on zero diag
        p += g_dinv[j] * g_H0T[c * NF + j];
    float h = g_dinv[j] * p + b_gcn[o1];
    hs[t] = fmaxf(h, 0.f);
    __syncthreads();

    if (t < 16) {
        float acc = bout[t];
        #pragma unroll 8
        for (int q = 0; q < 160; ++q) acc += hs[q] * Ws[q * 16 + t];
        out[((size_t)b * 1024 + n) * 16 + t] = acc;
    }
}

// ------------------------------------------------------------------ launch ---
extern "C" void kernel_launch(void* const* d_in, const int* in_sizes, int n_in,
                              void* d_out, int out_size) {
    const float* x        = (const float*)d_in[0];  // (4,1024,10,16)
    const float* supports = (const float*)d_in[3];  // (10240,10240)
    const float* W_gcn    = (const float*)d_in[6];  // (16,16)
    const float* b_gcn    = (const float*)d_in[7];  // (16,)
    const float* W_out    = (const float*)d_in[8];  // (160,16)
    const float* b_out    = (const float*)d_in[9];  // (16,)
    float* out = (float*)d_out;

    k0_h0t<<<NF / 256, 256>>>(x, W_gcn);
    k1_degpart<<<dim3(NF / 1024, 128), 256>>>(supports);
    k2a_dinv<<<NF / 256, 256>>>(supports);
    k2b_gt<<<dim3(NF / 1024, CDIM), 256>>>(0);
    k3_gemm<<<dim3(NF / MTILE, KSPLIT), 256>>>(supports);
    k4_epilogue<<<dim3(1024, 4), 160>>>(b_gcn, W_out, b_out, out);
}